// round 17
// baseline (speedup 1.0000x reference)
#include <cuda_runtime.h>
#include <cuda_bf16.h>
#include <math.h>
#include <stdint.h>

#define HEADS   8
#define PTS     4
#define CH      256
#define MAXROWS 32768

// Scratch (__device__ globals per allocation-free rule)
__device__ uint32_t g_vb[MAXROWS * CH / 2];     // v = value@W_val, packed bf16x2
__device__ float    g_offlg[MAXROWS * 96];      // [off(64) | logits(32)] per row
__device__ uint32_t g_attnb[MAXROWS * CH / 2];  // sampled output, packed bf16x2
__device__ uint32_t g_Wvalp[CH * CH / 2];       // bf16x2-packed W_val
__device__ uint32_t g_Woutp[CH * CH / 2];       // bf16x2-packed W_out

// Streams/events (created before capture).
static cudaStream_t s_side = nullptr;
static cudaEvent_t  e_fork = nullptr, e_v0 = nullptr, e_v1 = nullptr,
                    e_s[4] = {nullptr, nullptr, nullptr, nullptr},
                    e_g3 = nullptr;
namespace {
struct StreamInit {
    StreamInit() {
        cudaStreamCreateWithFlags(&s_side, cudaStreamNonBlocking);
        cudaEventCreateWithFlags(&e_fork, cudaEventDisableTiming);
        cudaEventCreateWithFlags(&e_v0,   cudaEventDisableTiming);
        cudaEventCreateWithFlags(&e_v1,   cudaEventDisableTiming);
        for (int i = 0; i < 4; i++)
            cudaEventCreateWithFlags(&e_s[i], cudaEventDisableTiming);
        cudaEventCreateWithFlags(&e_g3,   cudaEventDisableTiming);
    }
} s_init;
}

__device__ __forceinline__ uint32_t f2tf32(float x) {
    uint32_t r;
    asm("cvt.rna.tf32.f32 %0, %1;" : "=r"(r) : "f"(x));
    return r;
}
// pack2(lo, hi): lo -> bits[0:16), hi -> bits[16:32)
__device__ __forceinline__ uint32_t pack2(float lo, float hi) {
    uint32_t r;
    asm("cvt.rn.bf16x2.f32 %0, %1, %2;" : "=r"(r) : "f"(hi), "f"(lo));
    return r;
}
__device__ __forceinline__ void cpasync16(void* dst_smem, const void* src, bool pred) {
    uint32_t d = (uint32_t)__cvta_generic_to_shared(dst_smem);
    int sz = pred ? 16 : 0;
    asm volatile("cp.async.cg.shared.global [%0], [%1], 16, %2;\n"
                 :: "r"(d), "l"(src), "r"(sz));
}

// ===========================================================================
// bf16 tensor-core GEMM (m16n8k16), cp.async 3-stage (R11/R13-proven config).
// ===========================================================================
#define ALD_F 40
#define ALD_H 20
#define BLD   136
#define ASZ_F (128 * ALD_F)
#define ASZ_H (128 * ALD_H)
#define BSZ_P (16 * BLD)
#define NSTG  3

template<bool ABF16, bool OUTBF16>
__global__ __launch_bounds__(256) void gemm_bf16(
    const void* __restrict__ Av, const uint32_t* __restrict__ Bp,
    const float* __restrict__ bias, const float* __restrict__ resid,
    void* __restrict__ Cv, int M, int N, int K)
{
    extern __shared__ __align__(16) uint32_t smemw[];
    constexpr int ASZ = ABF16 ? ASZ_H : ASZ_F;
    uint32_t* Asm = smemw;
    uint32_t* Bsm = smemw + NSTG * ASZ;

    const int tid  = threadIdx.x;
    const int lane = tid & 31;
    const int warp = tid >> 5;
    const int wm   = warp & 1;
    const int wn   = warp >> 1;
    const int m0   = blockIdx.y * 128;
    const int n0   = blockIdx.x * 128;
    const int lr   = lane >> 2;
    const int lc   = lane & 3;

    float acc[4][4][4];
#pragma unroll
    for (int i = 0; i < 4; i++)
#pragma unroll
        for (int j = 0; j < 4; j++)
#pragma unroll
            for (int v = 0; v < 4; v++) acc[i][j][v] = 0.f;

    const int nk = K >> 5;

    auto stage_load = [&](int s, int k0) {
        uint32_t* As = Asm + s * ASZ;
        uint32_t* Bs = Bsm + s * BSZ_P;
        if (ABF16) {
            const __nv_bfloat16* A = (const __nv_bfloat16*)Av;
#pragma unroll
            for (int i = 0; i < 2; i++) {
                int f = tid + i * 256;
                int r = f >> 2, c = f & 3;
                cpasync16(&As[r * ALD_H + c * 4],
                          &A[(size_t)(m0 + r) * K + k0 + c * 8], true);
            }
        } else {
            const float* A = (const float*)Av;
#pragma unroll
            for (int i = 0; i < 4; i++) {
                int f = tid + i * 256;
                int r = f >> 3, c4 = f & 7;
                cpasync16(&As[r * ALD_F + c4 * 4],
                          &A[(size_t)(m0 + r) * K + k0 + c4 * 4], true);
            }
        }
#pragma unroll
        for (int i = 0; i < 2; i++) {
            int f  = tid + i * 256;
            int kp = f >> 5;
            int c4 = f & 31;
            int n  = n0 + c4 * 4;
            cpasync16(&Bs[kp * BLD + c4 * 4],
                      &Bp[(size_t)((k0 >> 1) + kp) * N + n], n < N);
        }
        asm volatile("cp.async.commit_group;\n");
    };

    stage_load(0, 0);
    if (nk > 1) stage_load(1, 32);

    uint32_t af[2][4][4];
    uint32_t bf[2][4][2];

    auto frag_load = [&](const uint32_t* As, const uint32_t* Bs, int buf, int ks) {
#pragma unroll
        for (int ma = 0; ma < 4; ma++) {
            int r = wm * 64 + ma * 16 + lr;
            if (ABF16) {
                af[buf][ma][0] = As[r * ALD_H + (ks >> 1) + lc];
                af[buf][ma][1] = As[(r + 8) * ALD_H + (ks >> 1) + lc];
                af[buf][ma][2] = As[r * ALD_H + (ks >> 1) + 4 + lc];
                af[buf][ma][3] = As[(r + 8) * ALD_H + (ks >> 1) + 4 + lc];
            } else {
                const float* Af = (const float*)As;
                float2 a0 = *(const float2*)&Af[r * ALD_F + ks + 2 * lc];
                float2 a1 = *(const float2*)&Af[(r + 8) * ALD_F + ks + 2 * lc];
                float2 a2 = *(const float2*)&Af[r * ALD_F + ks + 8 + 2 * lc];
                float2 a3 = *(const float2*)&Af[(r + 8) * ALD_F + ks + 8 + 2 * lc];
                af[buf][ma][0] = pack2(a0.x, a0.y);
                af[buf][ma][1] = pack2(a1.x, a1.y);
                af[buf][ma][2] = pack2(a2.x, a2.y);
                af[buf][ma][3] = pack2(a3.x, a3.y);
            }
        }
#pragma unroll
        for (int na = 0; na < 4; na++) {
            int n = wn * 32 + na * 8 + lr;
            bf[buf][na][0] = Bs[((ks >> 1) + lc) * BLD + n];
            bf[buf][na][1] = Bs[((ks >> 1) + 4 + lc) * BLD + n];
        }
    };

    for (int kt = 0; kt < nk; kt++) {
        if (kt + 1 < nk) asm volatile("cp.async.wait_group 1;\n");
        else             asm volatile("cp.async.wait_group 0;\n");
        __syncthreads();
        if (kt + 2 < nk) stage_load((kt + 2) % NSTG, (kt + 2) * 32);

        const uint32_t* As = Asm + (kt % NSTG) * ASZ;
        const uint32_t* Bs = Bsm + (kt % NSTG) * BSZ_P;

        frag_load(As, Bs, 0, 0);
#pragma unroll
        for (int s = 0; s < 2; s++) {
            int cur = s & 1, nxt = cur ^ 1;
            if (s == 0) frag_load(As, Bs, nxt, 16);
#pragma unroll
            for (int ma = 0; ma < 4; ma++)
#pragma unroll
                for (int na = 0; na < 4; na++) {
                    asm volatile(
                        "mma.sync.aligned.m16n8k16.row.col.f32.bf16.bf16.f32 "
                        "{%0,%1,%2,%3}, {%4,%5,%6,%7}, {%8,%9}, {%0,%1,%2,%3};\n"
                        : "+f"(acc[ma][na][0]), "+f"(acc[ma][na][1]),
                          "+f"(acc[ma][na][2]), "+f"(acc[ma][na][3])
                        : "r"(af[cur][ma][0]), "r"(af[cur][ma][1]),
                          "r"(af[cur][ma][2]), "r"(af[cur][ma][3]),
                          "r"(bf[cur][na][0]), "r"(bf[cur][na][1]));
                }
        }
        __syncthreads();
    }

#pragma unroll
    for (int ma = 0; ma < 4; ma++) {
        int r0 = m0 + wm * 64 + ma * 16 + lr;
        int r1 = r0 + 8;
#pragma unroll
        for (int na = 0; na < 4; na++) {
            int c = n0 + wn * 32 + na * 8 + lc * 2;
            if (c < N) {
                float2 bv = *(const float2*)&bias[c];
                float v00 = acc[ma][na][0] + bv.x;
                float v01 = acc[ma][na][1] + bv.y;
                float v10 = acc[ma][na][2] + bv.x;
                float v11 = acc[ma][na][3] + bv.y;
                if (OUTBF16) {
                    uint32_t* Cb = (uint32_t*)Cv;
                    Cb[((size_t)r0 * N + c) >> 1] = pack2(v00, v01);
                    Cb[((size_t)r1 * N + c) >> 1] = pack2(v10, v11);
                } else {
                    float* C = (float*)Cv;
                    if (resid) {
                        float2 r0v = *(const float2*)&resid[(size_t)r0 * N + c];
                        float2 r1v = *(const float2*)&resid[(size_t)r1 * N + c];
                        v00 += r0v.x; v01 += r0v.y;
                        v10 += r1v.x; v11 += r1v.y;
                    }
                    *(float2*)&C[(size_t)r0 * N + c] = make_float2(v00, v01);
                    *(float2*)&C[(size_t)r1 * N + c] = make_float2(v10, v11);
                }
            }
        }
    }
}

// ===========================================================================
// tf32 GEMM for offsets/logits: tile 128(M) x 96(N) x 32(K).
// NOW 3-stage cp.async + double-buffered fragments (R5 mechanism applied).
// smem = 3*(ASZ2+BSZ2)*4 = 94KB -> 2 CTA/SM.
// ===========================================================================
#define ALD2 36
#define BLD2 100
#define ASZ2 (128 * ALD2)
#define BSZ2 (32 * BLD2)
#define NST96 3
#define SMEM96 (NST96 * (ASZ2 + BSZ2) * 4)

__global__ __launch_bounds__(256) void gemm_tf32_96(
    const float* __restrict__ A,
    const float* __restrict__ W_off, const float* __restrict__ W_attn,
    const float* __restrict__ b_off, const float* __restrict__ b_attn,
    float* __restrict__ C, int M)
{
    constexpr int N = 96, K = 256;
    extern __shared__ __align__(16) float smem[];
    float* Asm = smem;
    float* Bsm = smem + NST96 * ASZ2;

    const int tid  = threadIdx.x;
    const int lane = tid & 31;
    const int warp = tid >> 5;
    const int wm   = warp & 1;
    const int wn   = warp >> 1;
    const int m0   = blockIdx.y * 128;
    const int lr   = lane >> 2;
    const int lc   = lane & 3;

    float acc[4][3][4];
#pragma unroll
    for (int i = 0; i < 4; i++)
#pragma unroll
        for (int j = 0; j < 3; j++)
#pragma unroll
            for (int v = 0; v < 4; v++) acc[i][j][v] = 0.f;

    const int nk = K >> 5;   // 8

    auto stage_load = [&](int s, int k0) {
        float* As = Asm + s * ASZ2;
        float* Bs = Bsm + s * BSZ2;
#pragma unroll
        for (int i = 0; i < 4; i++) {
            int f  = tid + i * 256;
            int r  = f >> 3;
            int c4 = f & 7;
            cpasync16(&As[r * ALD2 + c4 * 4],
                      &A[(size_t)(m0 + r) * K + k0 + c4 * 4], true);
        }
#pragma unroll
        for (int i = 0; i < 3; i++) {
            int f   = tid + i * 256;
            int kk  = f / 24;
            int col = (f - kk * 24) * 4;
            const float* src = (col < 64)
                ? &W_off[(size_t)(k0 + kk) * 64 + col]
                : &W_attn[(size_t)(k0 + kk) * 32 + (col - 64)];
            cpasync16(&Bs[kk * BLD2 + col], src, true);
        }
        asm volatile("cp.async.commit_group;\n");
    };

    stage_load(0, 0);
    stage_load(1, 32);

    uint32_t af[2][4][4];
    uint32_t bfr[2][3][2];

    auto frag_load = [&](const float* As, const float* Bs, int buf, int ks) {
#pragma unroll
        for (int ma = 0; ma < 4; ma++) {
            int r = wm * 64 + ma * 16 + lr;
            af[buf][ma][0] = f2tf32(As[r * ALD2 + ks + lc]);
            af[buf][ma][1] = f2tf32(As[(r + 8) * ALD2 + ks + lc]);
            af[buf][ma][2] = f2tf32(As[r * ALD2 + ks + 4 + lc]);
            af[buf][ma][3] = f2tf32(As[(r + 8) * ALD2 + ks + 4 + lc]);
        }
#pragma unroll
        for (int na = 0; na < 3; na++) {
            int n = wn * 24 + na * 8 + lr;
            bfr[buf][na][0] = f2tf32(Bs[(ks + lc) * BLD2 + n]);
            bfr[buf][na][1] = f2tf32(Bs[(ks + 4 + lc) * BLD2 + n]);
        }
    };

    for (int kt = 0; kt < nk; kt++) {
        if (kt + 1 < nk) asm volatile("cp.async.wait_group 1;\n");
        else             asm volatile("cp.async.wait_group 0;\n");
        __syncthreads();
        if (kt + 2 < nk) stage_load((kt + 2) % NST96, (kt + 2) * 32);

        const float* As = Asm + (kt % NST96) * ASZ2;
        const float* Bs = Bsm + (kt % NST96) * BSZ2;

        frag_load(As, Bs, 0, 0);
#pragma unroll
        for (int s = 0; s < 4; s++) {
            int cur = s & 1, nxt = cur ^ 1;
            if (s < 3) frag_load(As, Bs, nxt, (s + 1) * 8);
#pragma unroll
            for (int ma = 0; ma < 4; ma++)
#pragma unroll
                for (int na = 0; na < 3; na++) {
                    asm volatile(
                        "mma.sync.aligned.m16n8k8.row.col.f32.tf32.tf32.f32 "
                        "{%0,%1,%2,%3}, {%4,%5,%6,%7}, {%8,%9}, {%0,%1,%2,%3};\n"
                        : "+f"(acc[ma][na][0]), "+f"(acc[ma][na][1]),
                          "+f"(acc[ma][na][2]), "+f"(acc[ma][na][3])
                        : "r"(af[cur][ma][0]), "r"(af[cur][ma][1]),
                          "r"(af[cur][ma][2]), "r"(af[cur][ma][3]),
                          "r"(bfr[cur][na][0]), "r"(bfr[cur][na][1]));
                }
        }
        __syncthreads();
    }

#pragma unroll
    for (int ma = 0; ma < 4; ma++) {
        int r0 = m0 + wm * 64 + ma * 16 + lr;
        int r1 = r0 + 8;
#pragma unroll
        for (int na = 0; na < 3; na++) {
            int c = wn * 24 + na * 8 + lc * 2;
            float2 bv = (c < 64) ? *(const float2*)&b_off[c]
                                 : *(const float2*)&b_attn[c - 64];
            *(float2*)&C[(size_t)r0 * N + c] =
                make_float2(acc[ma][na][0] + bv.x, acc[ma][na][1] + bv.y);
            *(float2*)&C[(size_t)r1 * N + c] =
                make_float2(acc[ma][na][2] + bv.x, acc[ma][na][3] + bv.y);
        }
    }
}

// ---------------------------------------------------------------------------
// Fused weight packing: W_val + W_out in one launch (R9-proven).
// ---------------------------------------------------------------------------
__global__ void pack_weights(const float* __restrict__ Wval, uint32_t* __restrict__ Pval,
                             const float* __restrict__ Wout, uint32_t* __restrict__ Pout)
{
    const int NPK = (CH / 2) * (CH / 4);
    int i = blockIdx.x * blockDim.x + threadIdx.x;
    const float* W = (i < NPK) ? Wval : Wout;
    uint32_t*    P = (i < NPK) ? Pval : Pout;
    int j  = (i < NPK) ? i : i - NPK;
    int kp = j / (CH / 4);
    int c  = (j - kp * (CH / 4)) * 4;
    float4 a = *(const float4*)&W[(size_t)(2 * kp) * CH + c];
    float4 b = *(const float4*)&W[(size_t)(2 * kp + 1) * CH + c];
    uint4 o;
    o.x = pack2(a.x, b.x);
    o.y = pack2(a.y, b.y);
    o.z = pack2(a.z, b.z);
    o.w = pack2(a.w, b.w);
    *(uint4*)&P[(size_t)kp * CH + c] = o;
}

// ---------------------------------------------------------------------------
// Deformable bilinear sampling over bf16 v, two-phase, 8 rows/block
// (R13-proven). row0 allows split launches for pipelining.
// ---------------------------------------------------------------------------
__global__ __launch_bounds__(256, 5) void sample_kernel(
    const uint32_t* __restrict__ v, const float* __restrict__ offlg,
    uint32_t* __restrict__ outb,
    const int* __restrict__ hptr, const int* __restrict__ wptr, int row0)
{
    const int h = *hptr, w = *wptr;
    const int HW = h * w;
    const int tid = threadIdx.x;

    __shared__ float4 swgt[256];
    __shared__ int4   soff[256];

    // Phase 1: all 256 threads, one per (row, head, point)
    {
        const int r    = tid >> 5;
        const int head = (tid >> 2) & 7;
        const int p    = tid & 3;
        const int row  = row0 + blockIdx.x * 8 + r;

        const int b  = row / HW;
        const int q  = row - b * HW;
        const int qy = q / w;
        const int qx = q - qy * w;
        (void)b;

        const float* base = offlg + row * 96;
        float4 lgv = *(const float4*)(base + 64 + head * 4);
        float mx = fmaxf(fmaxf(lgv.x, lgv.y), fmaxf(lgv.z, lgv.w));
        float e0 = __expf(lgv.x - mx), e1 = __expf(lgv.y - mx);
        float e2 = __expf(lgv.z - mx), e3 = __expf(lgv.w - mx);
        float inv = 1.f / (e0 + e1 + e2 + e3);
        float ep = (p == 0) ? e0 : (p == 1) ? e1 : (p == 2) ? e2 : e3;
        float aw = ep * inv;

        float2 of = *(const float2*)(base + head * 8 + p * 2);
        float ix = (float)qx + of.x;
        float iy = (float)qy + of.y;
        float xf = floorf(ix), yf = floorf(iy);
        int x0 = (int)xf, y0 = (int)yf;
        float wx1 = ix - xf, wy1 = iy - yf;
        float wx0 = 1.f - wx1, wy0 = 1.f - wy1;

        bool vx0 = (unsigned)x0 < (unsigned)w;
        bool vx1 = (unsigned)(x0 + 1) < (unsigned)w;
        bool vy0 = (unsigned)y0 < (unsigned)h;
        bool vy1 = (unsigned)(y0 + 1) < (unsigned)h;

        int x0c = min(max(x0, 0), w - 1);
        int x1c = min(max(x0 + 1, 0), w - 1);
        int y0c = min(max(y0, 0), h - 1);
        int y1c = min(max(y0 + 1, 0), h - 1);

        float4 wg;
        wg.x = (vy0 && vx0) ? wx0 * wy0 * aw : 0.f;
        wg.y = (vy0 && vx1) ? wx1 * wy0 * aw : 0.f;
        wg.z = (vy1 && vx0) ? wx0 * wy1 * aw : 0.f;
        wg.w = (vy1 && vx1) ? wx1 * wy1 * aw : 0.f;

        int r0 = (y0c * w) << 7, r1 = (y1c * w) << 7;
        int4 off;
        off.x = r0 + (x0c << 7);
        off.y = r0 + (x1c << 7);
        off.z = r1 + (x0c << 7);
        off.w = r1 + (x1c << 7);

        swgt[tid] = wg;
        soff[tid] = off;
    }
    __syncthreads();

    // Phase 2: 32 threads per row, 4 lanes/head, 8 channels/lane
    const int rr   = tid >> 5;
    const int t31  = tid & 31;
    const int head = t31 >> 2;
    const int l4   = t31 & 3;
    const int row  = row0 + blockIdx.x * 8 + rr;
    const int b    = row / HW;

    const uint32_t* vb = v + ((b * HW) << 7) + head * 16 + l4 * 4;
    const int cb = rr * 32 + head * 4;

    float acc[8];
#pragma unroll
    for (int i = 0; i < 8; i++) acc[i] = 0.f;

#pragma unroll
    for (int p = 0; p < PTS; p++) {
        float4 wg = swgt[cb + p];
        int4   of = soff[cb + p];

        uint4 c0 = *(const uint4*)(vb + of.x);
        uint4 c1 = *(const uint4*)(vb + of.y);
        uint4 c2 = *(const uint4*)(vb + of.z);
        uint4 c3 = *(const uint4*)(vb + of.w);

#pragma unroll
        for (int k = 0; k < 4; k++) {
            uint32_t w0 = (&c0.x)[k], w1 = (&c1.x)[k], w2 = (&c2.x)[k], w3 = (&c3.x)[k];
            float2 f0 = __bfloat1622float2(*(__nv_bfloat162*)&w0);
            float2 f1 = __bfloat1622float2(*(__nv_bfloat162*)&w1);
            float2 f2 = __bfloat1622float2(*(__nv_bfloat162*)&w2);
            float2 f3 = __bfloat1622float2(*(__nv_bfloat162*)&w3);
            acc[2 * k]     = fmaf(wg.x, f0.x, acc[2 * k]);
            acc[2 * k + 1] = fmaf(wg.x, f0.y, acc[2 * k + 1]);
            acc[2 * k]     = fmaf(wg.y, f1.x, acc[2 * k]);
            acc[2 * k + 1] = fmaf(wg.y, f1.y, acc[2 * k + 1]);
            acc[2 * k]     = fmaf(wg.z, f2.x, acc[2 * k]);
            acc[2 * k + 1] = fmaf(wg.z, f2.y, acc[2 * k + 1]);
            acc[2 * k]     = fmaf(wg.w, f3.x, acc[2 * k]);
            acc[2 * k + 1] = fmaf(wg.w, f3.y, acc[2 * k + 1]);
        }
    }

    uint4 pk;
    pk.x = pack2(acc[0], acc[1]);
    pk.y = pack2(acc[2], acc[3]);
    pk.z = pack2(acc[4], acc[5]);
    pk.w = pack2(acc[6], acc[7]);
    *(uint4*)(outb + (row << 7) + head * 16 + l4 * 4) = pk;
}

// ---------------------------------------------------------------------------

extern "C" void kernel_launch(void* const* d_in, const int* in_sizes, int n_in,
                              void* d_out, int out_size)
{
    const float* query  = (const float*)d_in[0];
    const float* value  = (const float*)d_in[1];
    const float* W_off  = (const float*)d_in[2];
    const float* b_off  = (const float*)d_in[3];
    const float* W_attn = (const float*)d_in[4];
    const float* b_attn = (const float*)d_in[5];
    const float* W_val  = (const float*)d_in[6];
    const float* b_val  = (const float*)d_in[7];
    const float* W_out  = (const float*)d_in[8];
    const float* b_out  = (const float*)d_in[9];
    const int*   hp     = (const int*)d_in[10];
    const int*   wp     = (const int*)d_in[11];
    float* out = (float*)d_out;

    const int K = in_sizes[2] / (HEADS * PTS * 2);   // 256
    const int M = in_sizes[0] / K;                   // 32768
    const int N = in_sizes[6] / K;                   // 256
    const int Mh = M / 2;                            // 16384 (= one batch)
    const int Mq = M / 4;                            // 8192 (pipeline chunk)

    float *gofflg;
    uint32_t *gvb, *gattnb, *gWvalp, *gWoutp;
    cudaGetSymbolAddress((void**)&gvb,    g_vb);
    cudaGetSymbolAddress((void**)&gofflg, g_offlg);
    cudaGetSymbolAddress((void**)&gattnb, g_attnb);
    cudaGetSymbolAddress((void**)&gWvalp, g_Wvalp);
    cudaGetSymbolAddress((void**)&gWoutp, g_Woutp);

    auto g1 = gemm_bf16<false, true>;
    auto g3 = gemm_bf16<true, false>;
    constexpr int SMEM_G1 = (NSTG * (ASZ_F + BSZ_P)) * 4;
    constexpr int SMEM_G3 = (NSTG * (ASZ_H + BSZ_P)) * 4;

    cudaFuncSetAttribute(gemm_tf32_96, cudaFuncAttributeMaxDynamicSharedMemorySize, SMEM96);
    cudaFuncSetAttribute(g1, cudaFuncAttributeMaxDynamicSharedMemorySize, SMEM_G1);
    cudaFuncSetAttribute(g3, cudaFuncAttributeMaxDynamicSharedMemorySize, SMEM_G3);

    // Fork.
    cudaEventRecord(e_fork, 0);
    cudaStreamWaitEvent(s_side, e_fork, 0);

    // side: pack -> g1 batch0 -> e_v0 -> g1 batch1 -> e_v1
    pack_weights<<<64, 256, 0, s_side>>>(W_val, gWvalp, W_out, gWoutp);
    g1<<<dim3(N / 128, Mh / 128), 256, SMEM_G1, s_side>>>(
        value, gWvalp, b_val, nullptr, gvb, Mh, N, K);
    cudaEventRecord(e_v0, s_side);
    g1<<<dim3(N / 128, Mh / 128), 256, SMEM_G1, s_side>>>(
        value + (size_t)Mh * 256, gWvalp, b_val, nullptr,
        gvb + (size_t)Mh * 128, Mh, N, K);
    cudaEventRecord(e_v1, s_side);

    // main: offsets/logits GEMM (full M, 3-stage)
    gemm_tf32_96<<<dim3(1, M / 128), 256, SMEM96>>>(
        query, W_off, W_attn, b_off, b_attn, gofflg, M);

    // main: 4-chunk sample pipeline; side: g3 per chunk, gated by e_s[c].
    for (int c = 0; c < 4; c++) {
        if (c == 0) cudaStreamWaitEvent(0, e_v0, 0);
        if (c == 2) cudaStreamWaitEvent(0, e_v1, 0);
        sample_kernel<<<Mq / 8, 256>>>(gvb, gofflg, gattnb, hp, wp, c * Mq);
        cudaEventRecord(e_s[c], 0);

        cudaStreamWaitEvent(s_side, e_s[c], 0);
        g3<<<dim3(N / 128, Mq / 128), 256, SMEM_G3, s_side>>>(
            gattnb + (size_t)c * Mq * 128, gWoutp, b_out,
            query + (size_t)c * Mq * 256, out + (size_t)c * Mq * 256, Mq, N, K);
    }
    cudaEventRecord(e_g3, s_side);
    cudaStreamWaitEvent(0, e_g3, 0);
}